// round 9
// baseline (speedup 1.0000x reference)
#include <cuda_runtime.h>

#define BATCH 16
#define NPIX (1024 * 1024)
#define NVEC (NPIX / 4)
#define NACC 21
#define BPG 4                     // batches per group (48 MB src -> fits L2 easily)
#define NGROUP (BATCH / BPG)      // 4 groups
#define TPB 256
#define GX 512                    // 2048 blocks per launch -> good wave balance

// Scratch (allocation-free per harness rules)
__device__ double g_acc[BATCH][NACC];

__global__ void zero_kernel() {
    int i = blockIdx.x * blockDim.x + threadIdx.x;
    if (i < BATCH * NACC) ((double*)g_acc)[i] = 0.0;
}

// Raw moments for batches [base, base+BPG).
// src: default loads (evict_normal -> resident in L2 for the apply kernel)
// dst: .cs streaming loads (read once)
// Plain grid-stride loop body: let ptxas schedule loads (no manual front-batching;
// R8 showed 12 front-batched LDGs cause cross-CTA L1tex-queue contention).
__global__ void __launch_bounds__(TPB) reduce_kernel(const float* __restrict__ src,
                                                     const float* __restrict__ dst,
                                                     int base) {
    const int b = base + blockIdx.y;
    const float4* A0 = (const float4*)(src + (size_t)b * 3 * NPIX);
    const float4* A1 = A0 + NVEC;
    const float4* A2 = A1 + NVEC;
    const float4* B0 = (const float4*)(dst + (size_t)b * 3 * NPIX);
    const float4* B1 = B0 + NVEC;
    const float4* B2 = B1 + NVEC;

    float acc[NACC];
#pragma unroll
    for (int k = 0; k < NACC; k++) acc[k] = 0.0f;

    const int stride = GX * TPB;
    for (int i = blockIdx.x * TPB + threadIdx.x; i < NVEC; i += stride) {
        float4 a0 = A0[i], a1 = A1[i], a2 = A2[i];
        float4 b0 = __ldcs(B0 + i), b1 = __ldcs(B1 + i), b2 = __ldcs(B2 + i);
#define LANE(c)                                                                 \
        {                                                                       \
            float x0 = a0.c, x1 = a1.c, x2 = a2.c;                              \
            float y0 = b0.c, y1 = b1.c, y2 = b2.c;                              \
            acc[0] += x0;  acc[1] += x1;  acc[2] += x2;                         \
            acc[3] += y0;  acc[4] += y1;  acc[5] += y2;                         \
            acc[6]  += x0 * x0; acc[7]  += x0 * x1; acc[8]  += x0 * x2;         \
            acc[9]  += x1 * x1; acc[10] += x1 * x2; acc[11] += x2 * x2;         \
            acc[12] += y0 * x0; acc[13] += y0 * x1; acc[14] += y0 * x2;         \
            acc[15] += y1 * x0; acc[16] += y1 * x1; acc[17] += y1 * x2;         \
            acc[18] += y2 * x0; acc[19] += y2 * x1; acc[20] += y2 * x2;         \
        }
        LANE(x) LANE(y) LANE(z) LANE(w)
#undef LANE
    }

    __shared__ float s[NACC][TPB / 32];
    const int lane = threadIdx.x & 31;
    const int warp = threadIdx.x >> 5;
#pragma unroll
    for (int k = 0; k < NACC; k++) {
        float v = acc[k];
#pragma unroll
        for (int o = 16; o > 0; o >>= 1) v += __shfl_down_sync(0xffffffffu, v, o);
        if (lane == 0) s[k][warp] = v;
    }
    __syncthreads();
    if (threadIdx.x < NACC) {
        float v = 0.0f;
#pragma unroll
        for (int w = 0; w < TPB / 32; w++) v += s[threadIdx.x][w];
        atomicAdd(&g_acc[b][threadIdx.x], (double)v);
    }
}

// Apply for batches [base, base+BPG). Thread 0 of each block solves the 3x3
// system from g_acc (complete across the launch boundary), then streams.
__global__ void __launch_bounds__(TPB) apply_kernel(const float* __restrict__ src,
                                                    float* __restrict__ out,
                                                    int base) {
    const int b = base + blockIdx.y;
    __shared__ float sh_coef[12];

    if (threadIdx.x == 0) {
        const double* a = g_acc[b];
        const double n = (double)NPIX;
        double mA[3] = {a[0] / n, a[1] / n, a[2] / n};
        double mB[3] = {a[3] / n, a[4] / n, a[5] / n};
        double AA[3][3];
        AA[0][0] = a[6]  - n * mA[0] * mA[0] + 0.001;
        AA[0][1] = a[7]  - n * mA[0] * mA[1];
        AA[0][2] = a[8]  - n * mA[0] * mA[2];
        AA[1][1] = a[9]  - n * mA[1] * mA[1] + 0.001;
        AA[1][2] = a[10] - n * mA[1] * mA[2];
        AA[2][2] = a[11] - n * mA[2] * mA[2] + 0.001;
        AA[1][0] = AA[0][1]; AA[2][0] = AA[0][2]; AA[2][1] = AA[1][2];
        double BA[3][3];
#pragma unroll
        for (int i = 0; i < 3; i++)
#pragma unroll
            for (int j = 0; j < 3; j++)
                BA[i][j] = a[12 + 3 * i + j] - n * mB[i] * mA[j];

        double c00 =  (AA[1][1] * AA[2][2] - AA[1][2] * AA[2][1]);
        double c01 = -(AA[1][0] * AA[2][2] - AA[1][2] * AA[2][0]);
        double c02 =  (AA[1][0] * AA[2][1] - AA[1][1] * AA[2][0]);
        double c10 = -(AA[0][1] * AA[2][2] - AA[0][2] * AA[2][1]);
        double c11 =  (AA[0][0] * AA[2][2] - AA[0][2] * AA[2][0]);
        double c12 = -(AA[0][0] * AA[2][1] - AA[0][1] * AA[2][0]);
        double c20 =  (AA[0][1] * AA[1][2] - AA[0][2] * AA[1][1]);
        double c21 = -(AA[0][0] * AA[1][2] - AA[0][2] * AA[1][0]);
        double c22 =  (AA[0][0] * AA[1][1] - AA[0][1] * AA[1][0]);
        double det = AA[0][0] * c00 + AA[0][1] * c01 + AA[0][2] * c02;
        double id = 1.0 / det;
        double inv[3][3] = {{c00 * id, c10 * id, c20 * id},
                            {c01 * id, c11 * id, c21 * id},
                            {c02 * id, c12 * id, c22 * id}};
#pragma unroll
        for (int i = 0; i < 3; i++) {
            double xi[3];
#pragma unroll
            for (int j = 0; j < 3; j++)
                xi[j] = BA[i][0] * inv[0][j] + BA[i][1] * inv[1][j] + BA[i][2] * inv[2][j];
            sh_coef[3 * i + 0] = (float)xi[0];
            sh_coef[3 * i + 1] = (float)xi[1];
            sh_coef[3 * i + 2] = (float)xi[2];
            sh_coef[9 + i] = (float)(mB[i] - (xi[0] * mA[0] + xi[1] * mA[1] + xi[2] * mA[2]));
        }
    }
    __syncthreads();

    const float x00 = sh_coef[0], x01 = sh_coef[1], x02 = sh_coef[2];
    const float x10 = sh_coef[3], x11 = sh_coef[4], x12 = sh_coef[5];
    const float x20 = sh_coef[6], x21 = sh_coef[7], x22 = sh_coef[8];
    const float o0 = sh_coef[9], o1 = sh_coef[10], o2 = sh_coef[11];

    const float4* A0 = (const float4*)(src + (size_t)b * 3 * NPIX);
    const float4* A1 = A0 + NVEC;
    const float4* A2 = A1 + NVEC;
    float4* O0 = (float4*)(out + (size_t)b * 3 * NPIX);
    float4* O1 = O0 + NVEC;
    float4* O2 = O1 + NVEC;

    const int stride = GX * TPB;
    for (int i = blockIdx.x * TPB + threadIdx.x; i < NVEC; i += stride) {
        // src should hit L2 (loaded by reduce_kernel just before); .cs = last use
        float4 a0 = __ldcs(A0 + i), a1 = __ldcs(A1 + i), a2 = __ldcs(A2 + i);
        float4 r0, r1, r2;
#define LANE(c)                                                \
        r0.c = x00 * a0.c + x01 * a1.c + x02 * a2.c + o0;      \
        r1.c = x10 * a0.c + x11 * a1.c + x12 * a2.c + o1;      \
        r2.c = x20 * a0.c + x21 * a1.c + x22 * a2.c + o2;
        LANE(x) LANE(y) LANE(z) LANE(w)
#undef LANE
        __stcs(O0 + i, r0);
        __stcs(O1 + i, r1);
        __stcs(O2 + i, r2);
    }
}

extern "C" void kernel_launch(void* const* d_in, const int* in_sizes, int n_in,
                              void* d_out, int out_size) {
    const float* src = (const float*)d_in[0];
    const float* dst = (const float*)d_in[1];
    float* out = (float*)d_out;

    zero_kernel<<<2, 256>>>();
    for (int p = 0; p < NGROUP; p++) {
        const int base = p * BPG;
        dim3 grid(GX, BPG);
        reduce_kernel<<<grid, TPB>>>(src, dst, base);
        apply_kernel<<<grid, TPB>>>(src, out, base);
    }
}

// round 10
// speedup vs baseline: 1.3716x; 1.3716x over previous
#include <cuda_runtime.h>

#define BATCH 16
#define NPIX (1024 * 1024)
#define NVEC (NPIX / 4)
#define NACC 21
#define BPG 8                     // batches per group: 96 MB src resident in 126 MB L2
#define NGROUP (BATCH / BPG)      // 2 groups
#define TPB 256
#define GX 148                    // blocks per batch -> grid 1184 = 8/SM exactly;
                                  // ~6.9 loop iterations per block (pipelined loads)

// Scratch (allocation-free per harness rules)
__device__ double g_acc[BATCH][NACC];

__global__ void zero_kernel() {
    int i = blockIdx.x * blockDim.x + threadIdx.x;
    if (i < BATCH * NACC) ((double*)g_acc)[i] = 0.0;
}

// Raw moments for batches [base, base+BPG).
// src: default loads (evict_normal -> resident in L2 for the apply kernel)
// dst: .cs streaming loads (read once, don't displace src)
__global__ void __launch_bounds__(TPB) reduce_kernel(const float* __restrict__ src,
                                                     const float* __restrict__ dst,
                                                     int base) {
    const int b = base + blockIdx.y;
    const float4* A0 = (const float4*)(src + (size_t)b * 3 * NPIX);
    const float4* A1 = A0 + NVEC;
    const float4* A2 = A1 + NVEC;
    const float4* B0 = (const float4*)(dst + (size_t)b * 3 * NPIX);
    const float4* B1 = B0 + NVEC;
    const float4* B2 = B1 + NVEC;

    float acc[NACC];
#pragma unroll
    for (int k = 0; k < NACC; k++) acc[k] = 0.0f;

    const int stride = GX * TPB;
    for (int i = blockIdx.x * TPB + threadIdx.x; i < NVEC; i += stride) {
        float4 a0 = A0[i], a1 = A1[i], a2 = A2[i];
        float4 b0 = __ldcs(B0 + i), b1 = __ldcs(B1 + i), b2 = __ldcs(B2 + i);
#define LANE(c)                                                                 \
        {                                                                       \
            float x0 = a0.c, x1 = a1.c, x2 = a2.c;                              \
            float y0 = b0.c, y1 = b1.c, y2 = b2.c;                              \
            acc[0] += x0;  acc[1] += x1;  acc[2] += x2;                         \
            acc[3] += y0;  acc[4] += y1;  acc[5] += y2;                         \
            acc[6]  += x0 * x0; acc[7]  += x0 * x1; acc[8]  += x0 * x2;         \
            acc[9]  += x1 * x1; acc[10] += x1 * x2; acc[11] += x2 * x2;         \
            acc[12] += y0 * x0; acc[13] += y0 * x1; acc[14] += y0 * x2;         \
            acc[15] += y1 * x0; acc[16] += y1 * x1; acc[17] += y1 * x2;         \
            acc[18] += y2 * x0; acc[19] += y2 * x1; acc[20] += y2 * x2;         \
        }
        LANE(x) LANE(y) LANE(z) LANE(w)
#undef LANE
    }

    __shared__ float s[NACC][TPB / 32];
    const int lane = threadIdx.x & 31;
    const int warp = threadIdx.x >> 5;
#pragma unroll
    for (int k = 0; k < NACC; k++) {
        float v = acc[k];
#pragma unroll
        for (int o = 16; o > 0; o >>= 1) v += __shfl_down_sync(0xffffffffu, v, o);
        if (lane == 0) s[k][warp] = v;
    }
    __syncthreads();
    if (threadIdx.x < NACC) {
        float v = 0.0f;
#pragma unroll
        for (int w = 0; w < TPB / 32; w++) v += s[threadIdx.x][w];
        atomicAdd(&g_acc[b][threadIdx.x], (double)v);
    }
}

// Apply for batches [base, base+BPG). Thread 0 of each block solves the 3x3
// system from g_acc (complete across the launch boundary), then streams.
__global__ void __launch_bounds__(TPB) apply_kernel(const float* __restrict__ src,
                                                    float* __restrict__ out,
                                                    int base) {
    const int b = base + blockIdx.y;
    __shared__ float sh_coef[12];

    if (threadIdx.x == 0) {
        const double* a = g_acc[b];
        const double n = (double)NPIX;
        double mA[3] = {a[0] / n, a[1] / n, a[2] / n};
        double mB[3] = {a[3] / n, a[4] / n, a[5] / n};
        double AA[3][3];
        AA[0][0] = a[6]  - n * mA[0] * mA[0] + 0.001;
        AA[0][1] = a[7]  - n * mA[0] * mA[1];
        AA[0][2] = a[8]  - n * mA[0] * mA[2];
        AA[1][1] = a[9]  - n * mA[1] * mA[1] + 0.001;
        AA[1][2] = a[10] - n * mA[1] * mA[2];
        AA[2][2] = a[11] - n * mA[2] * mA[2] + 0.001;
        AA[1][0] = AA[0][1]; AA[2][0] = AA[0][2]; AA[2][1] = AA[1][2];
        double BA[3][3];
#pragma unroll
        for (int i = 0; i < 3; i++)
#pragma unroll
            for (int j = 0; j < 3; j++)
                BA[i][j] = a[12 + 3 * i + j] - n * mB[i] * mA[j];

        double c00 =  (AA[1][1] * AA[2][2] - AA[1][2] * AA[2][1]);
        double c01 = -(AA[1][0] * AA[2][2] - AA[1][2] * AA[2][0]);
        double c02 =  (AA[1][0] * AA[2][1] - AA[1][1] * AA[2][0]);
        double c10 = -(AA[0][1] * AA[2][2] - AA[0][2] * AA[2][1]);
        double c11 =  (AA[0][0] * AA[2][2] - AA[0][2] * AA[2][0]);
        double c12 = -(AA[0][0] * AA[2][1] - AA[0][1] * AA[2][0]);
        double c20 =  (AA[0][1] * AA[1][2] - AA[0][2] * AA[1][1]);
        double c21 = -(AA[0][0] * AA[1][2] - AA[0][2] * AA[1][0]);
        double c22 =  (AA[0][0] * AA[1][1] - AA[0][1] * AA[1][0]);
        double det = AA[0][0] * c00 + AA[0][1] * c01 + AA[0][2] * c02;
        double id = 1.0 / det;
        double inv[3][3] = {{c00 * id, c10 * id, c20 * id},
                            {c01 * id, c11 * id, c21 * id},
                            {c02 * id, c12 * id, c22 * id}};
#pragma unroll
        for (int i = 0; i < 3; i++) {
            double xi[3];
#pragma unroll
            for (int j = 0; j < 3; j++)
                xi[j] = BA[i][0] * inv[0][j] + BA[i][1] * inv[1][j] + BA[i][2] * inv[2][j];
            sh_coef[3 * i + 0] = (float)xi[0];
            sh_coef[3 * i + 1] = (float)xi[1];
            sh_coef[3 * i + 2] = (float)xi[2];
            sh_coef[9 + i] = (float)(mB[i] - (xi[0] * mA[0] + xi[1] * mA[1] + xi[2] * mA[2]));
        }
    }
    __syncthreads();

    const float x00 = sh_coef[0], x01 = sh_coef[1], x02 = sh_coef[2];
    const float x10 = sh_coef[3], x11 = sh_coef[4], x12 = sh_coef[5];
    const float x20 = sh_coef[6], x21 = sh_coef[7], x22 = sh_coef[8];
    const float o0 = sh_coef[9], o1 = sh_coef[10], o2 = sh_coef[11];

    const float4* A0 = (const float4*)(src + (size_t)b * 3 * NPIX);
    const float4* A1 = A0 + NVEC;
    const float4* A2 = A1 + NVEC;
    float4* O0 = (float4*)(out + (size_t)b * 3 * NPIX);
    float4* O1 = O0 + NVEC;
    float4* O2 = O1 + NVEC;

    const int stride = GX * TPB;
    for (int i = blockIdx.x * TPB + threadIdx.x; i < NVEC; i += stride) {
        // src should hit L2 (loaded by reduce_kernel just before); .cs = last use
        float4 a0 = __ldcs(A0 + i), a1 = __ldcs(A1 + i), a2 = __ldcs(A2 + i);
        float4 r0, r1, r2;
#define LANE(c)                                                \
        r0.c = x00 * a0.c + x01 * a1.c + x02 * a2.c + o0;      \
        r1.c = x10 * a0.c + x11 * a1.c + x12 * a2.c + o1;      \
        r2.c = x20 * a0.c + x21 * a1.c + x22 * a2.c + o2;
        LANE(x) LANE(y) LANE(z) LANE(w)
#undef LANE
        __stcs(O0 + i, r0);
        __stcs(O1 + i, r1);
        __stcs(O2 + i, r2);
    }
}

extern "C" void kernel_launch(void* const* d_in, const int* in_sizes, int n_in,
                              void* d_out, int out_size) {
    const float* src = (const float*)d_in[0];
    const float* dst = (const float*)d_in[1];
    float* out = (float*)d_out;

    zero_kernel<<<2, 256>>>();
    for (int p = 0; p < NGROUP; p++) {
        const int base = p * BPG;
        dim3 grid(GX, BPG);
        reduce_kernel<<<grid, TPB>>>(src, dst, base);
        apply_kernel<<<grid, TPB>>>(src, out, base);
    }
}